// round 2
// baseline (speedup 1.0000x reference)
#include <cuda_runtime.h>
#include <cuda_bf16.h>
#include <math.h>

#define H_DIM 2
#define L_LAYERS 4
#define R_RELS 16
#define B_BASES 8
#define N_NODES 1000000
#define E_EDGES 16000000
#define SCAN_CHUNK 1024
#define SCAN_BLOCKS ((N_NODES + SCAN_CHUNK - 1) / SCAN_CHUNK)   // 977

// ---- device scratch (allocation-free rule) --------------------------------
__device__ float2 g_x[N_NODES];
__device__ float2 g_y[N_NODES];
__device__ float2 g_skip[N_NODES];
__device__ int2   g_payload[E_EDGES];     // {src | type<<20, norm bits}
__device__ int    g_cnt[N_NODES];
__device__ int    g_row[N_NODES + 1];
__device__ int    g_cursor[N_NODES];
__device__ int    g_bsum[SCAN_CHUNK];
__device__ float  g_W[L_LAYERS * R_RELS * 4];
__device__ float  g_acc;

// ---------------------------------------------------------------------------
__global__ void compute_weights_kernel(const float* __restrict__ V,
                                       const float* __restrict__ comp) {
    int tid = threadIdx.x;
    if (tid >= L_LAYERS * R_RELS) return;
    int l = tid / R_RELS, r = tid % R_RELS;
    float w0 = 0.f, w1 = 0.f, w2 = 0.f, w3 = 0.f;
    #pragma unroll
    for (int b = 0; b < B_BASES; b++) {
        float c = comp[(l * R_RELS + r) * B_BASES + b];
        const float* v = V + ((l * B_BASES + b) * 4);
        w0 += c * v[0]; w1 += c * v[1]; w2 += c * v[2]; w3 += c * v[3];
    }
    g_W[tid * 4 + 0] = w0; g_W[tid * 4 + 1] = w1;
    g_W[tid * 4 + 2] = w2; g_W[tid * 4 + 3] = w3;
}

__global__ void init_x_kernel(const float2* __restrict__ feat) {
    int i = blockIdx.x * blockDim.x + threadIdx.x;
    if (i >= N_NODES) return;
    float2 f = feat[i];
    g_x[i] = f;
    g_skip[i] = f;
}

__global__ void zero_kernel() {
    int i = blockIdx.x * blockDim.x + threadIdx.x;
    if (i == 0) { g_acc = 0.f; g_row[N_NODES] = E_EDGES; }
    if (i < N_NODES) g_cnt[i] = 0;
}

// ---- counting-sort by dst -------------------------------------------------
__global__ void hist_kernel(const int4* __restrict__ dst4) {
    int i = blockIdx.x * blockDim.x + threadIdx.x;
    if (i >= E_EDGES / 4) return;
    int4 d = dst4[i];
    atomicAdd(&g_cnt[d.x], 1);
    atomicAdd(&g_cnt[d.y], 1);
    atomicAdd(&g_cnt[d.z], 1);
    atomicAdd(&g_cnt[d.w], 1);
}

__global__ void scan1_kernel() {   // per-chunk sums
    __shared__ int s[SCAN_CHUNK];
    int idx = blockIdx.x * SCAN_CHUNK + threadIdx.x;
    int v = (idx < N_NODES) ? g_cnt[idx] : 0;
    s[threadIdx.x] = v;
    __syncthreads();
    for (int off = SCAN_CHUNK / 2; off > 0; off >>= 1) {
        if (threadIdx.x < off) s[threadIdx.x] += s[threadIdx.x + off];
        __syncthreads();
    }
    if (threadIdx.x == 0) g_bsum[blockIdx.x] = s[0];
}

__global__ void scan2_kernel() {   // exclusive scan of chunk sums (1 block)
    __shared__ int s[SCAN_CHUNK];
    int t = threadIdx.x;
    int v = (t < SCAN_BLOCKS) ? g_bsum[t] : 0;
    s[t] = v;
    __syncthreads();
    #pragma unroll
    for (int off = 1; off < SCAN_CHUNK; off <<= 1) {
        int x = (t >= off) ? s[t - off] : 0;
        __syncthreads();
        s[t] += x;
        __syncthreads();
    }
    g_bsum[t] = s[t] - v;          // exclusive
}

__global__ void scan3_kernel() {   // chunk-local exclusive scan + offset
    __shared__ int s[SCAN_CHUNK];
    int t = threadIdx.x;
    int idx = blockIdx.x * SCAN_CHUNK + t;
    int v = (idx < N_NODES) ? g_cnt[idx] : 0;
    s[t] = v;
    __syncthreads();
    #pragma unroll
    for (int off = 1; off < SCAN_CHUNK; off <<= 1) {
        int x = (t >= off) ? s[t - off] : 0;
        __syncthreads();
        s[t] += x;
        __syncthreads();
    }
    if (idx < N_NODES) {
        int row = g_bsum[blockIdx.x] + s[t] - v;
        g_row[idx] = row;
        g_cursor[idx] = row;
    }
}

__global__ void scatter_kernel(const int4* __restrict__ src4,
                               const int4* __restrict__ dst4,
                               const int4* __restrict__ type4,
                               const float4* __restrict__ norm4) {
    int i = blockIdx.x * blockDim.x + threadIdx.x;
    if (i >= E_EDGES / 4) return;
    int4   s  = src4[i];
    int4   d  = dst4[i];
    int4   t  = type4[i];
    float4 nm = norm4[i];
    int   ss[4] = {s.x, s.y, s.z, s.w};
    int   dd[4] = {d.x, d.y, d.z, d.w};
    int   tt[4] = {t.x, t.y, t.z, t.w};
    float nn[4] = {nm.x, nm.y, nm.z, nm.w};
    #pragma unroll
    for (int k = 0; k < 4; k++) {
        int slot = atomicAdd(&g_cursor[dd[k]], 1);
        g_payload[slot] = make_int2(ss[k] | (tt[k] << 20),
                                    __float_as_int(nn[k]));
    }
}

// ---- layer: one thread per dst node, register accumulation ----------------
__global__ void layer_kernel(int l, const float2* __restrict__ xin,
                             float2* __restrict__ xout,
                             const float* __restrict__ bias) {
    __shared__ float sW[R_RELS * 4];
    if (threadIdx.x < R_RELS * 4)
        sW[threadIdx.x] = g_W[l * R_RELS * 4 + threadIdx.x];
    __syncthreads();

    int n = blockIdx.x * blockDim.x + threadIdx.x;
    if (n >= N_NODES) return;

    int start = g_row[n];
    int end   = g_row[n + 1];
    float ax = __ldg(&bias[2 * l]);
    float ay = __ldg(&bias[2 * l + 1]);

    #pragma unroll 4
    for (int e = start; e < end; e++) {
        int2  p   = g_payload[e];
        int   src = p.x & 0xFFFFF;
        int   typ = p.x >> 20;
        float nrm = __int_as_float(p.y);
        float2 xs = xin[src];
        const float* w = &sW[typ * 4];
        ax += (xs.x * w[0] + xs.y * w[2]) * nrm;
        ay += (xs.x * w[1] + xs.y * w[3]) * nrm;
    }

    if (l < L_LAYERS - 1) { ax = fmaxf(ax, 0.f); ay = fmaxf(ay, 0.f); }
    if (l & 1) {
        float2 sk = g_skip[n];
        ax += sk.x; ay += sk.y;
        g_skip[n] = make_float2(ax, ay);
    }
    xout[n] = make_float2(ax, ay);
}

// ---- final dot + sigmoid --------------------------------------------------
__global__ void dot_kernel(const float4* __restrict__ w4,
                           const float4* __restrict__ x4) {
    const int total4 = (N_NODES * H_DIM) / 4;
    float sum = 0.f;
    for (int i = blockIdx.x * blockDim.x + threadIdx.x; i < total4;
         i += gridDim.x * blockDim.x) {
        float4 a = x4[i];
        float4 b = w4[i];
        sum += a.x * b.x + a.y * b.y + a.z * b.z + a.w * b.w;
    }
    #pragma unroll
    for (int off = 16; off > 0; off >>= 1)
        sum += __shfl_down_sync(0xFFFFFFFFu, sum, off);
    __shared__ float ws[8];
    int lane = threadIdx.x & 31, wid = threadIdx.x >> 5;
    if (lane == 0) ws[wid] = sum;
    __syncthreads();
    if (wid == 0) {
        sum = (lane < (blockDim.x >> 5)) ? ws[lane] : 0.f;
        #pragma unroll
        for (int off = 4; off > 0; off >>= 1)
            sum += __shfl_down_sync(0xFFFFFFFFu, sum, off);
        if (lane == 0) atomicAdd(&g_acc, sum);
    }
}

__global__ void finalize_kernel(const float* __restrict__ b_mlp,
                                float* __restrict__ out) {
    float logit = g_acc + b_mlp[0];
    out[0] = 1.f / (1.f + expf(-logit));
}

// ---------------------------------------------------------------------------
extern "C" void kernel_launch(void* const* d_in, const int* in_sizes, int n_in,
                              void* d_out, int out_size) {
    const float* features  = (const float*)d_in[0];
    const float* norm      = (const float*)d_in[1];
    const float* V         = (const float*)d_in[2];
    const float* comp      = (const float*)d_in[3];
    const float* bias      = (const float*)d_in[4];
    const float* w_mlp     = (const float*)d_in[5];
    const float* b_mlp     = (const float*)d_in[6];
    const int*   edge_src  = (const int*)d_in[7];
    const int*   edge_dst  = (const int*)d_in[8];
    const int*   edge_type = (const int*)d_in[9];
    float*       out       = (float*)d_out;

    const int TB = 256;
    const int node_blocks = (N_NODES + TB - 1) / TB;
    const int edge_blocks = (E_EDGES / 4 + TB - 1) / TB;

    compute_weights_kernel<<<1, 64>>>(V, comp);
    init_x_kernel<<<node_blocks, TB>>>((const float2*)features);
    zero_kernel<<<node_blocks, TB>>>();

    // counting sort by dst -> CSR
    hist_kernel<<<edge_blocks, TB>>>((const int4*)edge_dst);
    scan1_kernel<<<SCAN_BLOCKS, SCAN_CHUNK>>>();
    scan2_kernel<<<1, SCAN_CHUNK>>>();
    scan3_kernel<<<SCAN_BLOCKS, SCAN_CHUNK>>>();
    scatter_kernel<<<edge_blocks, TB>>>((const int4*)edge_src,
                                        (const int4*)edge_dst,
                                        (const int4*)edge_type,
                                        (const float4*)norm);

    // 4 RGCN layers, ping-pong x between g_x and g_y; final result in g_x
    float2* bufs[2] = {nullptr, nullptr};
    // resolve device symbol addresses is not allowed at capture time via API;
    // instead use a tiny dispatch: layer kernels take raw pointers obtained
    // from the symbols inside device code is not possible here, so use
    // cudaGetSymbolAddress outside capture? Not graph-safe restriction — it is
    // a host-side query, allowed. But simpler: alternate with a flag.
    (void)bufs;
    void* px = nullptr; void* py = nullptr;
    cudaGetSymbolAddress(&px, g_x);
    cudaGetSymbolAddress(&py, g_y);
    float2* fx = (float2*)px;
    float2* fy = (float2*)py;

    layer_kernel<<<node_blocks, TB>>>(0, fx, fy, bias);
    layer_kernel<<<node_blocks, TB>>>(1, fy, fx, bias);
    layer_kernel<<<node_blocks, TB>>>(2, fx, fy, bias);
    layer_kernel<<<node_blocks, TB>>>(3, fy, fx, bias);

    dot_kernel<<<1024, TB>>>((const float4*)w_mlp, (const float4*)fx);
    finalize_kernel<<<1, 1>>>(b_mlp, out);
}

// round 3
// speedup vs baseline: 1.1032x; 1.1032x over previous
#include <cuda_runtime.h>
#include <cuda_bf16.h>
#include <math.h>

#define H_DIM 2
#define L_LAYERS 4
#define R_RELS 16
#define B_BASES 8
#define N_NODES 1000000
#define E_EDGES 16000000

#define TILE_SHIFT 10
#define TILE_SIZE 1024
#define N_TILES ((N_NODES + TILE_SIZE - 1) / TILE_SIZE)   // 977

#define SC_THREADS 256
#define SC_CHUNK 4096
#define SC_PER_THREAD (SC_CHUNK / SC_THREADS)             // 16
#define SC_BLOCKS ((E_EDGES + SC_CHUNK - 1) / SC_CHUNK)   // 3907

// ---- device scratch (allocation-free rule) --------------------------------
__device__ float2 g_x[N_NODES];
__device__ float2 g_y[N_NODES];
__device__ float2 g_skip[N_NODES];
__device__ int2   g_payload[E_EDGES];       // {src|dl<<20, norm~type}
__device__ int    g_hist[N_TILES];
__device__ int    g_row[N_TILES + 1];
__device__ int    g_cursor[N_TILES];
__device__ float  g_W[L_LAYERS * R_RELS * 4];
__device__ float  g_acc;

// ---------------------------------------------------------------------------
__global__ void compute_weights_kernel(const float* __restrict__ V,
                                       const float* __restrict__ comp) {
    int tid = threadIdx.x;
    if (tid >= L_LAYERS * R_RELS) return;
    int l = tid / R_RELS, r = tid % R_RELS;
    float w0 = 0.f, w1 = 0.f, w2 = 0.f, w3 = 0.f;
    #pragma unroll
    for (int b = 0; b < B_BASES; b++) {
        float c = comp[(l * R_RELS + r) * B_BASES + b];
        const float* v = V + ((l * B_BASES + b) * 4);
        w0 += c * v[0]; w1 += c * v[1]; w2 += c * v[2]; w3 += c * v[3];
    }
    g_W[tid * 4 + 0] = w0; g_W[tid * 4 + 1] = w1;
    g_W[tid * 4 + 2] = w2; g_W[tid * 4 + 3] = w3;
}

__global__ void init_x_kernel(const float2* __restrict__ feat) {
    int i = blockIdx.x * blockDim.x + threadIdx.x;
    if (i >= N_NODES) return;
    float2 f = feat[i];
    g_x[i] = f;
    g_skip[i] = f;
}

__global__ void zero_kernel() {
    int i = blockIdx.x * blockDim.x + threadIdx.x;
    if (i == 0) g_acc = 0.f;
    if (i < N_TILES) g_hist[i] = 0;
}

// ---- tile histogram (smem-aggregated) -------------------------------------
__global__ void hist_kernel(const int* __restrict__ dst) {
    __shared__ int sh[TILE_SIZE];   // >= N_TILES
    for (int b = threadIdx.x; b < TILE_SIZE; b += blockDim.x) sh[b] = 0;
    __syncthreads();
    for (int i = blockIdx.x * blockDim.x + threadIdx.x; i < E_EDGES;
         i += gridDim.x * blockDim.x)
        atomicAdd(&sh[dst[i] >> TILE_SHIFT], 1);
    __syncthreads();
    for (int b = threadIdx.x; b < N_TILES; b += blockDim.x) {
        int c = sh[b];
        if (c) atomicAdd(&g_hist[b], c);
    }
}

// ---- exclusive scan over 977 bins (1 block) -------------------------------
__global__ void scan_kernel() {
    __shared__ int s[1024];
    int t = threadIdx.x;
    int v = (t < N_TILES) ? g_hist[t] : 0;
    s[t] = v;
    __syncthreads();
    #pragma unroll
    for (int off = 1; off < 1024; off <<= 1) {
        int x = (t >= off) ? s[t - off] : 0;
        __syncthreads();
        s[t] += x;
        __syncthreads();
    }
    if (t < N_TILES) {
        int ex = s[t] - v;
        g_row[t] = ex;
        g_cursor[t] = ex;
    }
    if (t == 0) g_row[N_TILES] = E_EDGES;
}

// ---- block-aggregated multisplit scatter ----------------------------------
__global__ void binscatter_kernel(const int* __restrict__ src,
                                  const int* __restrict__ dst,
                                  const int* __restrict__ type,
                                  const float* __restrict__ norm) {
    __shared__ int2 s_pay[SC_CHUNK];                 // 32 KB
    __shared__ unsigned short s_tile[SC_CHUNK];      // 8 KB
    __shared__ int s_hist[980];                      // ~3.8 KB
    __shared__ int s_base[980];                      // ~3.8 KB

    int base = blockIdx.x * SC_CHUNK;
    for (int b = threadIdx.x; b < 980; b += SC_THREADS) s_hist[b] = 0;
    __syncthreads();

    #pragma unroll
    for (int k = 0; k < SC_PER_THREAD; k++) {
        int li = k * SC_THREADS + threadIdx.x;
        int idx = base + li;
        if (idx < E_EDGES) {
            int s  = src[idx];
            int d  = dst[idx];
            int t  = type[idx];
            int nb = __float_as_int(norm[idx]);
            int tile = d >> TILE_SHIFT;
            int dl   = d & (TILE_SIZE - 1);
            s_pay[li]  = make_int2(s | (dl << 20), (nb & ~0xF) | t);
            s_tile[li] = (unsigned short)tile;
            atomicAdd(&s_hist[tile], 1);
        } else {
            s_tile[li] = 0xFFFF;
        }
    }
    __syncthreads();

    for (int b = threadIdx.x; b < N_TILES; b += SC_THREADS) {
        int c = s_hist[b];
        s_base[b] = c ? atomicAdd(&g_cursor[b], c) : 0;
        s_hist[b] = 0;
    }
    __syncthreads();

    #pragma unroll
    for (int k = 0; k < SC_PER_THREAD; k++) {
        int li = k * SC_THREADS + threadIdx.x;
        unsigned short tl = s_tile[li];
        if (tl != 0xFFFF) {
            int pos = s_base[tl] + atomicAdd(&s_hist[tl], 1);
            g_payload[pos] = s_pay[li];
        }
    }
}

// ---- layer: one block per 1024-node tile, smem accumulation ---------------
__global__ void layer_kernel(int l, const float2* __restrict__ xin,
                             float2* __restrict__ xout,
                             const float* __restrict__ bias) {
    __shared__ float acc[TILE_SIZE * 2];   // 8 KB
    __shared__ float sW[R_RELS * 4];

    int tid = threadIdx.x;
    if (tid < R_RELS * 4) sW[tid] = g_W[l * R_RELS * 4 + tid];
    float bx = __ldg(&bias[2 * l]);
    float by = __ldg(&bias[2 * l + 1]);
    for (int i = tid; i < TILE_SIZE; i += blockDim.x) {
        acc[2 * i]     = bx;
        acc[2 * i + 1] = by;
    }
    __syncthreads();

    int b = blockIdx.x;
    int start = g_row[b];
    int end   = g_row[b + 1];

    #pragma unroll 4
    for (int e = start + tid; e < end; e += blockDim.x) {
        int2 p = g_payload[e];
        int src = p.x & 0xFFFFF;
        int dl  = (p.x >> 20) & 0x3FF;
        int typ = p.y & 0xF;
        float nrm = __int_as_float(p.y & ~0xF);
        float2 xs = __ldg(&xin[src]);
        const float* w = &sW[typ * 4];
        atomicAdd(&acc[2 * dl],     (xs.x * w[0] + xs.y * w[2]) * nrm);
        atomicAdd(&acc[2 * dl + 1], (xs.x * w[1] + xs.y * w[3]) * nrm);
    }
    __syncthreads();

    int nbase = b << TILE_SHIFT;
    for (int i = tid; i < TILE_SIZE; i += blockDim.x) {
        int n = nbase + i;
        if (n >= N_NODES) break;
        float hx = acc[2 * i], hy = acc[2 * i + 1];
        if (l < L_LAYERS - 1) { hx = fmaxf(hx, 0.f); hy = fmaxf(hy, 0.f); }
        if (l & 1) {
            float2 sk = g_skip[n];
            hx += sk.x; hy += sk.y;
            g_skip[n] = make_float2(hx, hy);
        }
        xout[n] = make_float2(hx, hy);
    }
}

// ---- final dot + sigmoid --------------------------------------------------
__global__ void dot_kernel(const float4* __restrict__ w4,
                           const float4* __restrict__ x4) {
    const int total4 = (N_NODES * H_DIM) / 4;
    float sum = 0.f;
    for (int i = blockIdx.x * blockDim.x + threadIdx.x; i < total4;
         i += gridDim.x * blockDim.x) {
        float4 a = x4[i];
        float4 b = w4[i];
        sum += a.x * b.x + a.y * b.y + a.z * b.z + a.w * b.w;
    }
    #pragma unroll
    for (int off = 16; off > 0; off >>= 1)
        sum += __shfl_down_sync(0xFFFFFFFFu, sum, off);
    __shared__ float ws[8];
    int lane = threadIdx.x & 31, wid = threadIdx.x >> 5;
    if (lane == 0) ws[wid] = sum;
    __syncthreads();
    if (wid == 0) {
        sum = (lane < (blockDim.x >> 5)) ? ws[lane] : 0.f;
        #pragma unroll
        for (int off = 4; off > 0; off >>= 1)
            sum += __shfl_down_sync(0xFFFFFFFFu, sum, off);
        if (lane == 0) atomicAdd(&g_acc, sum);
    }
}

__global__ void finalize_kernel(const float* __restrict__ b_mlp,
                                float* __restrict__ out) {
    float logit = g_acc + b_mlp[0];
    out[0] = 1.f / (1.f + expf(-logit));
}

// ---------------------------------------------------------------------------
extern "C" void kernel_launch(void* const* d_in, const int* in_sizes, int n_in,
                              void* d_out, int out_size) {
    const float* features  = (const float*)d_in[0];
    const float* norm      = (const float*)d_in[1];
    const float* V         = (const float*)d_in[2];
    const float* comp      = (const float*)d_in[3];
    const float* bias      = (const float*)d_in[4];
    const float* w_mlp     = (const float*)d_in[5];
    const float* b_mlp     = (const float*)d_in[6];
    const int*   edge_src  = (const int*)d_in[7];
    const int*   edge_dst  = (const int*)d_in[8];
    const int*   edge_type = (const int*)d_in[9];
    float*       out       = (float*)d_out;

    const int TB = 256;
    const int node_blocks = (N_NODES + TB - 1) / TB;

    compute_weights_kernel<<<1, 64>>>(V, comp);
    init_x_kernel<<<node_blocks, TB>>>((const float2*)features);
    zero_kernel<<<node_blocks, TB>>>();

    hist_kernel<<<2048, TB>>>(edge_dst);
    scan_kernel<<<1, 1024>>>();
    binscatter_kernel<<<SC_BLOCKS, SC_THREADS>>>(edge_src, edge_dst,
                                                 edge_type, norm);

    void* px = nullptr; void* py = nullptr;
    cudaGetSymbolAddress(&px, g_x);
    cudaGetSymbolAddress(&py, g_y);
    float2* fx = (float2*)px;
    float2* fy = (float2*)py;

    layer_kernel<<<N_TILES, TB>>>(0, fx, fy, bias);
    layer_kernel<<<N_TILES, TB>>>(1, fy, fx, bias);
    layer_kernel<<<N_TILES, TB>>>(2, fx, fy, bias);
    layer_kernel<<<N_TILES, TB>>>(3, fy, fx, bias);

    dot_kernel<<<1024, TB>>>((const float4*)w_mlp, (const float4*)fx);
    finalize_kernel<<<1, 1>>>(b_mlp, out);
}